// round 4
// baseline (speedup 1.0000x reference)
#include <cuda_runtime.h>

#define CC   2
#define HH   200
#define WW   200
#define NN   200
#define HWN  (HH*WW*NN)
#define N8   (NN/8)                     // 25 groups of 8 n per (h,w)

// Factorized per-axis cell tables (int8):
//   g_cx[w*NN + n] = cx in {0,1}, or -1 if x outside [x1,x2]
//   g_cy[h*NN + n] = cy in {0,1}, or -1 if y outside [y1,y2]
__device__ signed char g_cx[WW * NN];
__device__ signed char g_cy[HH * NN];

__global__ void prep_kernel(const float* __restrict__ rois) {
    int idx = blockIdx.x * blockDim.x + threadIdx.x;   // [0, 2*200*200)
    if (idx >= 2 * WW * NN) return;

    int axis = idx / (WW * NN);     // 0 = x, 1 = y
    int rem  = idx % (WW * NN);
    int p    = rem / NN;            // pixel coord (w or h)
    int n    = rem % NN;

    float lo = rois[4 * n + (axis ? 1 : 0)];   // x1 or y1
    float hi = rois[4 * n + (axis ? 3 : 2)];   // x2 or y2
    float cl = fmaxf(hi - lo, 1.0f);
    // double-precision reciprocal so (p-lo)*s tracks fp32 CC*(p-lo)/cl to ~1 ulp
    float s  = (float)((double)CC / (double)cl);

    float pf = (float)p;
    signed char v = -1;
    if (pf >= lo && pf <= hi) {
        int c = (int)floorf((pf - lo) * s);
        c = min(max(c, 0), CC - 1);
        v = (signed char)c;
    }
    if (axis == 0) g_cx[p * NN + n] = v;
    else           g_cy[p * NN + n] = v;
}

// Block = 256 lanes spanning w (lanes >= 200 idle); blockIdx = (h, n8).
// cy bytes are BLOCK-UNIFORM -> uniform branch skips whole gather iterations
// (P(y outside) ~ 0.67 per n): no address math, no LDG, no wavefronts.
__global__ void __launch_bounds__(256)
crop_split_kernel(const float* __restrict__ data, float* __restrict__ out) {
    int w  = threadIdx.x;
    int bx = blockIdx.x;
    int n8 = bx % N8;
    int h  = bx / N8;
    if (w >= WW) return;

    int base = (h * WW + w) * NN + n8 * 8;     // 32B-aligned output segment

    // uniform across the block (depends on h, n only)
    uint2 cyu = *reinterpret_cast<const uint2*>(g_cy + h * NN + n8 * 8);
    // per-lane (depends on w, n)
    uint2 cxu = *reinterpret_cast<const uint2*>(g_cx + w * NN + n8 * 8);

    float v[8] = {0.f, 0.f, 0.f, 0.f, 0.f, 0.f, 0.f, 0.f};

    #pragma unroll
    for (int i = 0; i < 8; i++) {
        int cy = (int)(signed char)(((i < 4 ? cyu.x : cyu.y) >> (8 * (i & 3))) & 0xffu);
        if (cy >= 0) {                                   // uniform branch
            int cx = (int)(signed char)(((i < 4 ? cxu.x : cxu.y) >> (8 * (i & 3))) & 0xffu);
            if (cx >= 0) {                               // per-lane predicate
                int cell = cy * CC + cx;
                v[i] = __ldg(data + (size_t)cell * HWN + base + i);
            }
        }
    }

    float4* o = reinterpret_cast<float4*>(out + base);
    o[0] = make_float4(v[0], v[1], v[2], v[3]);
    o[1] = make_float4(v[4], v[5], v[6], v[7]);
}

extern "C" void kernel_launch(void* const* d_in, const int* in_sizes, int n_in,
                              void* d_out, int out_size) {
    const float* data = (const float*)d_in[0];   // (4, H, W, N) fp32
    const float* rois = (const float*)d_in[1];   // (N, 4) fp32
    float* out = (float*)d_out;                  // (H, W, N) fp32

    int prep_elems = 2 * WW * NN;                // 80000
    prep_kernel<<<(prep_elems + 255) / 256, 256>>>(rois);

    crop_split_kernel<<<HH * N8, 256>>>(data, out);   // 5000 blocks
}

// round 5
// speedup vs baseline: 1.2424x; 1.2424x over previous
#include <cuda_runtime.h>

#define CC   2
#define HH   200
#define WW   200
#define NN   200
#define HWN  (HH*WW*NN)
#define N8   (NN/8)                     // 25 groups of 8 n per (h,w)
#define NGROUPS (HH*WW*N8)              // 1,000,000 8n-groups
#define HALF    (NGROUPS/2)             // 500,000 (split at hw = 20000)

// Factorized per-axis cell tables (int8):
//   g_cx[w*NN + n] = cx in {0,1}, or -1 if x outside [x1,x2]
//   g_cy[h*NN + n] = cy in {0,1}, or -1 if y outside [y1,y2]
__device__ signed char g_cx[WW * NN];
__device__ signed char g_cy[HH * NN];

__global__ void prep_kernel(const float* __restrict__ rois) {
    int idx = blockIdx.x * blockDim.x + threadIdx.x;   // [0, 2*200*200)
    if (idx >= 2 * WW * NN) return;

    int axis = idx / (WW * NN);     // 0 = x, 1 = y
    int rem  = idx % (WW * NN);
    int p    = rem / NN;            // pixel coord (w or h)
    int n    = rem % NN;

    float lo = rois[4 * n + (axis ? 1 : 0)];   // x1 or y1
    float hi = rois[4 * n + (axis ? 3 : 2)];   // x2 or y2
    float cl = fmaxf(hi - lo, 1.0f);
    // double-precision reciprocal so (p-lo)*s tracks fp32 CC*(p-lo)/cl to ~1 ulp
    float s  = (float)((double)CC / (double)cl);

    float pf = (float)p;
    signed char v = -1;
    if (pf >= lo && pf <= hi) {
        int c = (int)floorf((pf - lo) * s);
        c = min(max(c, 0), CC - 1);
        v = (signed char)c;
    }
    if (axis == 0) g_cx[p * NN + n] = v;
    else           g_cy[p * NN + n] = v;
}

// One thread handles TWO 8n-groups from opposite halves of the image:
// 16 front-batched predicated gathers per thread (high MLP), lanes span
// consecutive n8 -> fully coalesced table loads and 512B warp stores.
__global__ void __launch_bounds__(256)
crop_split_kernel(const float* __restrict__ data, float* __restrict__ out) {
    int t = blockIdx.x * 256 + threadIdx.x;
    if (t >= HALF) return;

    float v[16];
    int   basev[2];

    #pragma unroll
    for (int g = 0; g < 2; g++) {
        int gi = t + g * HALF;          // group index in [0, NGROUPS)
        int n8 = gi % N8;
        int hw = gi / N8;
        int w  = hw % WW;
        int h  = hw / WW;
        int base = hw * NN + n8 * 8;    // 32B-aligned
        basev[g] = base;

        uint2 cxu = *reinterpret_cast<const uint2*>(g_cx + w * NN + n8 * 8);
        uint2 cyu = *reinterpret_cast<const uint2*>(g_cy + h * NN + n8 * 8);

        #pragma unroll
        for (int i = 0; i < 8; i++) {
            int cx = (int)(signed char)(((i < 4 ? cxu.x : cxu.y) >> (8 * (i & 3))) & 0xffu);
            int cy = (int)(signed char)(((i < 4 ? cyu.x : cyu.y) >> (8 * (i & 3))) & 0xffu);
            float val = 0.0f;
            if ((cx | cy) >= 0) {
                int cell = cy * CC + cx;
                val = __ldg(data + (size_t)cell * HWN + base + i);
            }
            v[g * 8 + i] = val;
        }
    }

    #pragma unroll
    for (int g = 0; g < 2; g++) {
        float4* o = reinterpret_cast<float4*>(out + basev[g]);
        o[0] = make_float4(v[g*8+0], v[g*8+1], v[g*8+2], v[g*8+3]);
        o[1] = make_float4(v[g*8+4], v[g*8+5], v[g*8+6], v[g*8+7]);
    }
}

extern "C" void kernel_launch(void* const* d_in, const int* in_sizes, int n_in,
                              void* d_out, int out_size) {
    const float* data = (const float*)d_in[0];   // (4, H, W, N) fp32
    const float* rois = (const float*)d_in[1];   // (N, 4) fp32
    float* out = (float*)d_out;                  // (H, W, N) fp32

    int prep_elems = 2 * WW * NN;                // 80000
    prep_kernel<<<(prep_elems + 255) / 256, 256>>>(rois);

    int blocks = (HALF + 255) / 256;             // 1954
    crop_split_kernel<<<blocks, 256>>>(data, out);
}